// round 3
// baseline (speedup 1.0000x reference)
#include <cuda_runtime.h>
#include <math.h>

#define NB 32

static constexpr int HGRID = 512;
static constexpr int HTHREADS = 256;
static constexpr int MGRID = 2048;
static constexpr int MTHREADS = 256;
static constexpr int NSLOT = 132;   // 4*32 bin slots + 4 scalar slots

// ---------------- quantile (exact radix select) state ----------------
struct QState {
    unsigned pref[2];    // current prefix (low-aligned), jobs: 0 -> 1% rank, 1 -> 99% rank
    unsigned rank[2];    // remaining rank within current group
    unsigned base[2];    // total count strictly less than current group
    unsigned eq[2];      // count equal to selected key (set at last pass)
    unsigned key[2];     // final selected 32-bit key
    unsigned succ[2];    // min key strictly greater than selected key
    int hist[2][256];
};
__device__ QState g_qs[2];           // one per input array

struct CRParams {
    float f_lo[2], f_hi[2], m_lo[2], m_hi[2];
    float preterm[2], t0[2], invstep[2];
    float vbc[2][NB];
};
__device__ CRParams g_p;

__device__ float g_part[NSLOT * MGRID];   // transposed partials: [slot][block]

// monotone float<->uint key mapping
__device__ __forceinline__ unsigned f2key(float f) {
    unsigned u = __float_as_uint(f);
    return (u & 0x80000000u) ? ~u : (u | 0x80000000u);
}
__device__ __forceinline__ float key2f(unsigned k) {
    unsigned u = (k & 0x80000000u) ? (k & 0x7FFFFFFFu) : ~k;
    return __uint_as_float(u);
}

__global__ void k_qinit(unsigned k01, unsigned k99) {
    int t = threadIdx.x;
    #pragma unroll
    for (int arr = 0; arr < 2; arr++) {
        int* h = &g_qs[arr].hist[0][0];
        for (int i = t; i < 512; i += blockDim.x) h[i] = 0;
        if (t == 0) {
            g_qs[arr].pref[0] = 0u;  g_qs[arr].pref[1] = 0u;
            g_qs[arr].rank[0] = k01; g_qs[arr].rank[1] = k99;
            g_qs[arr].base[0] = 0u;  g_qs[arr].base[1] = 0u;
            g_qs[arr].succ[0] = 0xFFFFFFFFu; g_qs[arr].succ[1] = 0xFFFFFFFFu;
        }
    }
}

__global__ void k_hist(const float* __restrict__ x, int arr, int pass, int N) {
    __shared__ int sh[2][256];
    int t = threadIdx.x;
    for (int i = t; i < 512; i += blockDim.x) (&sh[0][0])[i] = 0;
    __syncthreads();
    QState* qs = &g_qs[arr];
    int stride = gridDim.x * blockDim.x;
    int i0 = blockIdx.x * blockDim.x + t;
    if (pass == 0) {
        // both jobs share the empty prefix -> one histogram
        for (int i = i0; i < N; i += stride) {
            unsigned k = f2key(x[i]);
            atomicAdd(&sh[0][k >> 24], 1);
        }
    } else {
        unsigned p0 = qs->pref[0], p1 = qs->pref[1];
        int ms = 32 - 8 * pass;   // prefix compare shift
        int bs = 24 - 8 * pass;   // current byte shift
        for (int i = i0; i < N; i += stride) {
            unsigned k = f2key(x[i]);
            unsigned top = k >> ms;
            unsigned b = (k >> bs) & 255u;
            if (top == p0) atomicAdd(&sh[0][b], 1);
            if (top == p1) atomicAdd(&sh[1][b], 1);
        }
    }
    __syncthreads();
    for (int i = t; i < 512; i += blockDim.x) {
        int v = (&sh[0][0])[i];
        if (v) atomicAdd(&(&qs->hist[0][0])[i], v);
    }
}

__global__ void k_scan(int pass) {
    int t = threadIdx.x;
    if (t < 4) {
        int arr = t >> 1, j = t & 1;
        QState* qs = &g_qs[arr];
        int jsel = (pass == 0) ? 0 : j;
        unsigned rank = qs->rank[j];
        unsigned cum = 0;
        int d = 0, c = 0;
        for (d = 0; d < 256; d++) {
            c = qs->hist[jsel][d];
            if (cum + (unsigned)c > rank) break;
            cum += (unsigned)c;
        }
        qs->pref[j] = (qs->pref[j] << 8) | (unsigned)d;
        qs->rank[j] = rank - cum;
        qs->base[j] += cum;
        if (pass == 3) { qs->key[j] = qs->pref[j]; qs->eq[j] = (unsigned)c; }
    }
    __syncthreads();
    // zero histograms for next pass / next graph replay
    for (int arr = 0; arr < 2; arr++) {
        int* h = &g_qs[arr].hist[0][0];
        for (int i = t; i < 512; i += blockDim.x) h[i] = 0;
    }
}

__global__ void k_succ(const float* __restrict__ x, int arr, int N) {
    __shared__ unsigned s0, s1;
    if (threadIdx.x == 0) { s0 = 0xFFFFFFFFu; s1 = 0xFFFFFFFFu; }
    __syncthreads();
    QState* qs = &g_qs[arr];
    unsigned k0 = qs->key[0], k1 = qs->key[1];
    unsigned m0 = 0xFFFFFFFFu, m1 = 0xFFFFFFFFu;
    int stride = gridDim.x * blockDim.x;
    for (int i = blockIdx.x * blockDim.x + threadIdx.x; i < N; i += stride) {
        unsigned k = f2key(x[i]);
        if (k > k0) m0 = min(m0, k);
        if (k > k1) m1 = min(m1, k);
    }
    atomicMin(&s0, m0);
    atomicMin(&s1, m1);
    __syncthreads();
    if (threadIdx.x == 0) {
        atomicMin(&qs->succ[0], s0);
        atomicMin(&qs->succ[1], s1);
    }
}

__global__ void k_prep(float frac01, float frac99, unsigned k01, unsigned k99) {
    float q01[2], q99[2];
    for (int arr = 0; arr < 2; arr++) {
        QState* qs = &g_qs[arr];
        // order stat k, and k+1 (handles duplicate spans via base+eq)
        float v = key2f(qs->key[0]);
        float vb = (qs->base[0] + qs->eq[0] >= k01 + 2u) ? v : key2f(qs->succ[0]);
        q01[arr] = v + frac01 * (vb - v);
        v = key2f(qs->key[1]);
        vb = (qs->base[1] + qs->eq[1] >= k99 + 2u) ? v : key2f(qs->succ[1]);
        q99[arr] = v + frac99 * (vb - v);
    }
    const float sigma_ratio = (float)(1.0 / 2.355);
    // term 0: pred = arr0 (y_true), target = arr1 (y_pred); term 1: swapped
    for (int term = 0; term < 2; term++) {
        int pa = term, ta = 1 - term;
        float flo = q01[ta], fhi = q99[ta];
        g_p.f_lo[term] = flo; g_p.f_hi[term] = fhi;
        g_p.m_lo[term] = q01[pa]; g_p.m_hi[term] = q99[pa];
        float fb = (fhi - flo) / (float)NB;
        float lo = flo + 0.5f * fb;
        float hi = fhi - 0.5f * fb;
        float step = (hi - lo) / (float)(NB - 1);
        float sd = 0.0f, prev = lo;
        for (int i = 0; i < NB; i++) {
            float v = lo + step * (float)i;
            g_p.vbc[term][i] = v;
            if (i) sd += (v - prev);
            prev = v;
        }
        float fs = (sd / (float)(NB - 1)) * sigma_ratio;   // mean(diff(vbc)) * sigma_ratio
        g_p.preterm[term] = 1.0f / (2.0f * fs * fs);
        g_p.t0[term] = g_p.vbc[term][0];
        g_p.invstep[term] = 1.0f / step;
    }
}

// ---------------- main Parzen accumulation kernel ----------------
__global__ void __launch_bounds__(MTHREADS) k_main(const float* __restrict__ A,
                                                   const float* __restrict__ B, int N) {
    __shared__ float s_sw0[NB], s_swx0[NB], s_sw1[NB], s_swx1[NB];
    __shared__ float s_vbc0[NB], s_vbc1[NB];
    __shared__ float s_sc[4];
    int t = threadIdx.x;
    if (t < NB) {
        s_sw0[t] = 0.f; s_swx0[t] = 0.f; s_sw1[t] = 0.f; s_swx1[t] = 0.f;
        s_vbc0[t] = g_p.vbc[0][t];
        s_vbc1[t] = g_p.vbc[1][t];
    }
    if (t < 4) s_sc[t] = 0.f;
    const float flo0 = g_p.f_lo[0], fhi0 = g_p.f_hi[0];
    const float mlo0 = g_p.m_lo[0], mhi0 = g_p.m_hi[0];
    const float pt0 = g_p.preterm[0], t00 = g_p.t0[0], is0 = g_p.invstep[0];
    const float flo1 = g_p.f_lo[1], fhi1 = g_p.f_hi[1];
    const float mlo1 = g_p.m_lo[1], mhi1 = g_p.m_hi[1];
    const float pt1 = g_p.preterm[1], t01 = g_p.t0[1], is1 = g_p.invstep[1];
    __syncthreads();

    float sx0 = 0.f, sxx0 = 0.f, sx1 = 0.f, sxx1 = 0.f;
    int stride = gridDim.x * blockDim.x;
    for (int i = blockIdx.x * blockDim.x + t; i < N; i += stride) {
        float a = A[i], bv = B[i];
        // ---- term 0: pred = y_true (A), target = y_pred (B) ----
        {
            float y = fminf(fmaxf(bv, flo0), fhi0);
            float x = fminf(fmaxf(a, mlo0), mhi0);
            sx0 += x; sxx0 += x * x;
            int b0 = __float2int_rn((y - t00) * is0);
            b0 = min(max(b0, 0), NB - 1);
            #pragma unroll
            for (int o = -2; o <= 2; o++) {
                int j = b0 + o;
                if (j >= 0 && j < NB) {
                    float d = y - s_vbc0[j];
                    float w = __expf(-pt0 * d * d);
                    atomicAdd(&s_sw0[j], w);
                    atomicAdd(&s_swx0[j], w * x);
                }
            }
        }
        // ---- term 1: pred = y_pred (B), target = y_true (A) ----
        {
            float y = fminf(fmaxf(a, flo1), fhi1);
            float x = fminf(fmaxf(bv, mlo1), mhi1);
            sx1 += x; sxx1 += x * x;
            int b0 = __float2int_rn((y - t01) * is1);
            b0 = min(max(b0, 0), NB - 1);
            #pragma unroll
            for (int o = -2; o <= 2; o++) {
                int j = b0 + o;
                if (j >= 0 && j < NB) {
                    float d = y - s_vbc1[j];
                    float w = __expf(-pt1 * d * d);
                    atomicAdd(&s_sw1[j], w);
                    atomicAdd(&s_swx1[j], w * x);
                }
            }
        }
    }
    atomicAdd(&s_sc[0], sx0);
    atomicAdd(&s_sc[1], sxx0);
    atomicAdd(&s_sc[2], sx1);
    atomicAdd(&s_sc[3], sxx1);
    __syncthreads();
    int blk = blockIdx.x;
    if (t < NB) {
        g_part[(0 * NB + t) * MGRID + blk] = s_sw0[t];
        g_part[(1 * NB + t) * MGRID + blk] = s_swx0[t];
        g_part[(2 * NB + t) * MGRID + blk] = s_sw1[t];
        g_part[(3 * NB + t) * MGRID + blk] = s_swx1[t];
    }
    if (t < 4) g_part[(128 + t) * MGRID + blk] = s_sc[t];
}

// ---------------- deterministic final reduction + scalar math ----------------
__global__ void k_final(float* __restrict__ out, int N) {
    __shared__ double s_tmp[NSLOT][4];
    __shared__ double s_tot[NSLOT];
    int t = threadIdx.x;
    int slot = t >> 2, sub = t & 3;
    if (slot < NSLOT) {
        double acc = 0.0;
        const float* p = &g_part[slot * MGRID];
        for (int b = sub; b < MGRID; b += 4) acc += (double)p[b];
        s_tmp[slot][sub] = acc;
    }
    __syncthreads();
    if (t < NSLOT)
        s_tot[t] = s_tmp[t][0] + s_tmp[t][1] + s_tmp[t][2] + s_tmp[t][3];
    __syncthreads();
    if (t == 0) {
        const double eps = 1.1920928955078125e-07;  // float32 eps
        double dN = (double)N;
        double eta_sum = 0.0;
        for (int term = 0; term < 2; term++) {
            const double* sw = &s_tot[term * 64];
            const double* swx = sw + NB;
            double sx = s_tot[128 + 2 * term];
            double sxx = s_tot[129 + 2 * term];
            double mean = sx / dN;
            double Ssw = 0.0, num = 0.0;
            for (int j = 0; j < NB; j++) {
                double m = swx[j] / (sw[j] + eps);
                double d = m - mean;
                num += sw[j] * d * d;
                Ssw += sw[j];
            }
            double bgv = num / (Ssw + eps);
            double var = (sxx - sx * sx / dN) / (dN - 1.0);   // ddof = 1
            eta_sum += bgv / (var + eps);
        }
        out[0] = (float)(-0.5 * eta_sum);
    }
}

extern "C" void kernel_launch(void* const* d_in, const int* in_sizes, int n_in,
                              void* d_out, int out_size) {
    const float* A = (const float*)d_in[0];   // y_true
    const float* B = (const float*)d_in[1];   // y_pred (result is symmetric in A<->B)
    int N = in_sizes[0];

    double n1 = (double)N - 1.0;
    double p01 = 0.01 * n1, p99 = 0.99 * n1;
    unsigned k01 = (unsigned)p01, k99 = (unsigned)p99;
    float f01 = (float)(p01 - (double)k01);
    float f99 = (float)(p99 - (double)k99);

    k_qinit<<<1, 256>>>(k01, k99);
    for (int pass = 0; pass < 4; pass++) {
        k_hist<<<HGRID, HTHREADS>>>(A, 0, pass, N);
        k_hist<<<HGRID, HTHREADS>>>(B, 1, pass, N);
        k_scan<<<1, 256>>>(pass);
    }
    k_succ<<<HGRID, HTHREADS>>>(A, 0, N);
    k_succ<<<HGRID, HTHREADS>>>(B, 1, N);
    k_prep<<<1, 1>>>(f01, f99, k01, k99);
    k_main<<<MGRID, MTHREADS>>>(A, B, N);
    k_final<<<1, 1024>>>((float*)d_out, N);
}

// round 4
// speedup vs baseline: 2.1644x; 2.1644x over previous
#include <cuda_runtime.h>
#include <math.h>

#define NB 32
static constexpr int HGRID   = 512;
static constexpr int HTHREADS= 256;
static constexpr int MGRID   = 2048;
static constexpr int MTHREADS= 256;

// ---------------- radix-select state: 4 jobs per array (k01, k01+1, k99, k99+1) ----
struct QS {
    unsigned pref[2][4];
    unsigned rank[2][4];
    unsigned key[2][4];
};
__device__ QS g_qs;
__device__ int g_hist[2][4][256];   // [array][job][bin]

struct Params {
    float f_lo[2], f_hi[2], m_lo[2], m_hi[2];
    float preterm[2], t0[2], invstep[2], step[2];
    float sw_scale, sx_scale[2];          // fixed-point scales
    float sw_inv, sx_inv[2];
};
__device__ Params g_p;

// per-block partials (exact integers for bins, fp32 for scalars)
__device__ unsigned g_hw[64 * MGRID];     // [term*32+bin][block]  sum round(w*Sw)
__device__ int      g_lw[64 * MGRID];     // [term*32+bin][block]  sum round(w*x*Sx)
__device__ float    g_sc[4 * MGRID];      // [scalar][block]  sx0,sxx0,sx1,sxx1

// monotone float<->uint key map
__device__ __forceinline__ unsigned f2key(float f) {
    unsigned u = __float_as_uint(f);
    return (u & 0x80000000u) ? ~u : (u | 0x80000000u);
}
__device__ __forceinline__ float key2f(unsigned k) {
    unsigned u = (k & 0x80000000u) ? (k & 0x7FFFFFFFu) : ~k;
    return __uint_as_float(u);
}

__global__ void k_qinit(unsigned k01, unsigned k99) {
    int t = threadIdx.x;
    int* h = &g_hist[0][0][0];
    for (int i = t; i < 2048; i += blockDim.x) h[i] = 0;
    if (t < 8) {
        int a = t >> 2, j = t & 3;
        g_qs.pref[a][j] = 0u;
        g_qs.rank[a][j] = (j < 2 ? k01 : k99) + (unsigned)(j & 1);
    }
}

// fused histogram: both arrays, all jobs, float4 loads
__global__ void __launch_bounds__(HTHREADS) k_hist(const float* __restrict__ A,
                                                   const float* __restrict__ B,
                                                   int pass, int N) {
    __shared__ int sh[8][256];
    int t = threadIdx.x;
    for (int i = t; i < 2048; i += HTHREADS) (&sh[0][0])[i] = 0;
    __syncthreads();

    const float4* A4 = (const float4*)A;
    const float4* B4 = (const float4*)B;
    int N4 = N >> 2;
    int stride = gridDim.x * HTHREADS;
    int i0 = blockIdx.x * HTHREADS + t;

    if (pass == 0) {
        int ca = (t & 3);           // copy for A rows 0..3
        int cb = 4 + (t & 3);       // copy for B rows 4..7
        for (int i = i0; i < N4; i += stride) {
            float4 va = A4[i], vb = B4[i];
            atomicAdd(&sh[ca][f2key(va.x) >> 24], 1);
            atomicAdd(&sh[ca][f2key(va.y) >> 24], 1);
            atomicAdd(&sh[ca][f2key(va.z) >> 24], 1);
            atomicAdd(&sh[ca][f2key(va.w) >> 24], 1);
            atomicAdd(&sh[cb][f2key(vb.x) >> 24], 1);
            atomicAdd(&sh[cb][f2key(vb.y) >> 24], 1);
            atomicAdd(&sh[cb][f2key(vb.z) >> 24], 1);
            atomicAdd(&sh[cb][f2key(vb.w) >> 24], 1);
        }
        // scalar tail
        if (i0 == 0) {
            for (int r = N4 << 2; r < N; r++) {
                atomicAdd(&sh[0][f2key(A[r]) >> 24], 1);
                atomicAdd(&sh[4][f2key(B[r]) >> 24], 1);
            }
        }
    } else {
        unsigned pa[4], pb[4];
        #pragma unroll
        for (int j = 0; j < 4; j++) { pa[j] = g_qs.pref[0][j]; pb[j] = g_qs.pref[1][j]; }
        int ms = 32 - 8 * pass, bs = 24 - 8 * pass;
        for (int i = i0; i < N4; i += stride) {
            float4 va = A4[i], vb = B4[i];
            float ea[4] = {va.x, va.y, va.z, va.w};
            float eb[4] = {vb.x, vb.y, vb.z, vb.w};
            #pragma unroll
            for (int e = 0; e < 4; e++) {
                unsigned k = f2key(ea[e]);
                unsigned top = k >> ms, b = (k >> bs) & 255u;
                #pragma unroll
                for (int j = 0; j < 4; j++)
                    if (top == pa[j]) atomicAdd(&sh[j][b], 1);
                k = f2key(eb[e]);
                top = k >> ms; b = (k >> bs) & 255u;
                #pragma unroll
                for (int j = 0; j < 4; j++)
                    if (top == pb[j]) atomicAdd(&sh[4 + j][b], 1);
            }
        }
        if (i0 == 0) {
            for (int r = N4 << 2; r < N; r++) {
                unsigned k = f2key(A[r]);
                unsigned top = k >> ms, b = (k >> bs) & 255u;
                for (int j = 0; j < 4; j++) if (top == pa[j]) atomicAdd(&sh[j][b], 1);
                k = f2key(B[r]); top = k >> ms; b = (k >> bs) & 255u;
                for (int j = 0; j < 4; j++) if (top == pb[j]) atomicAdd(&sh[4 + j][b], 1);
            }
        }
    }
    __syncthreads();
    for (int i = t; i < 2048; i += HTHREADS) {
        int v = (&sh[0][0])[i];
        if (v) {
            int row = i >> 8, bin = i & 255;
            int a = row >> 2;
            int j = (pass == 0) ? 0 : (row & 3);
            atomicAdd(&g_hist[a][j][bin], v);
        }
    }
}

// parallel scan: one warp per job (8 jobs), then zero histograms
__global__ void k_scan(int pass) {
    int t = threadIdx.x, warp = t >> 5, lane = t & 31;
    if (warp < 8) {
        int a = warp >> 2, jj = warp & 3;
        int jsel = (pass == 0) ? 0 : jj;
        const int* h = &g_hist[a][jsel][0];
        int c[8]; int ps = 0;
        #pragma unroll
        for (int k = 0; k < 8; k++) { c[k] = h[lane * 8 + k]; ps += c[k]; }
        // inclusive warp scan of per-lane totals
        int v = ps;
        #pragma unroll
        for (int off = 1; off < 32; off <<= 1) {
            int n = __shfl_up_sync(0xFFFFFFFFu, v, off);
            if (lane >= off) v += n;
        }
        unsigned excl = (unsigned)(v - ps);
        unsigned rank = g_qs.rank[a][jj];
        bool has = (rank >= excl) && (rank < excl + (unsigned)ps);
        if (has) {
            unsigned cum = excl; int d = 0;
            #pragma unroll
            for (int k = 0; k < 8; k++) {
                if (cum + (unsigned)c[k] > rank) { d = k; break; }
                cum += (unsigned)c[k];
            }
            unsigned np = (g_qs.pref[a][jj] << 8) | (unsigned)(lane * 8 + d);
            g_qs.pref[a][jj] = np;
            g_qs.rank[a][jj] = rank - cum;
            if (pass == 3) g_qs.key[a][jj] = np;
        }
    }
    __syncthreads();
    int* h = &g_hist[0][0][0];
    for (int i = t; i < 2048; i += blockDim.x) h[i] = 0;
}

__global__ void k_prep(float frac01, float frac99, int epb) {
    float q[2][2];
    for (int a = 0; a < 2; a++) {
        float v0 = key2f(g_qs.key[a][0]), v1 = key2f(g_qs.key[a][1]);
        q[a][0] = v0 + frac01 * (v1 - v0);
        v0 = key2f(g_qs.key[a][2]); v1 = key2f(g_qs.key[a][3]);
        q[a][1] = v0 + frac99 * (v1 - v0);
    }
    const float sigma_ratio = (float)(1.0 / 2.355);
    float xmax_all = 1.0f;
    for (int term = 0; term < 2; term++) {
        int pa = term, ta = 1 - term;
        float flo = q[ta][0], fhi = q[ta][1];
        g_p.f_lo[term] = flo; g_p.f_hi[term] = fhi;
        g_p.m_lo[term] = q[pa][0]; g_p.m_hi[term] = q[pa][1];
        float fb = (fhi - flo) / (float)NB;
        float lo = flo + 0.5f * fb;
        float hi = fhi - 0.5f * fb;
        float step = (hi - lo) / (float)(NB - 1);
        // mean(diff(linspace)) computed as in reference (f32)
        float sd = 0.0f, prev = lo;
        for (int i = 1; i < NB; i++) {
            float v = lo + step * (float)i;
            sd += (v - prev); prev = v;
        }
        float fs = (sd / (float)(NB - 1)) * sigma_ratio;
        g_p.preterm[term] = 1.0f / (2.0f * fs * fs);
        g_p.t0[term] = lo;
        g_p.step[term] = step;
        g_p.invstep[term] = 1.0f / step;
        float xm = fmaxf(fabsf(g_p.m_lo[term]), fabsf(g_p.m_hi[term]));
        if (xm < 1e-20f) xm = 1e-20f;
        // Sx: per-contribution |w*x*Sx| <= xm*Sx ; epb contributions per (bin,block)
        float sx = exp2f(floorf(log2f(1073741824.0f / ((float)epb * xm))));
        g_p.sx_scale[term] = sx;
        g_p.sx_inv[term] = 1.0f / sx;
        if (xm > xmax_all) xmax_all = xm;
    }
    float sw = exp2f(floorf(log2f(1073741824.0f / (float)epb)));   // w <= 1
    g_p.sw_scale = sw;
    g_p.sw_inv = 1.0f / sw;
}

// ---------------- main Parzen accumulation: packed 64-bit fixed-point atomics ----
__device__ __forceinline__ void accum5(float y, float x,
                                       float pt, float t0, float is, float step,
                                       float SW, float SX,
                                       unsigned long long* hist) {
    int b0 = __float2int_rn((y - t0) * is);
    b0 = min(max(b0, 0), NB - 1);
    float xs = x * SX;
    #pragma unroll
    for (int o = -2; o <= 2; o++) {
        int j = b0 + o;
        if (j >= 0 && j < NB) {
            float vj = fmaf((float)j, step, t0);
            float d = y - vj;
            float w = __expf(-pt * d * d);
            unsigned hw = __float2uint_rn(w * SW);
            int lw = __float2int_rn(w * xs);
            unsigned long long pk =
                ((unsigned long long)hw << 32) + (unsigned long long)(long long)lw;
            atomicAdd(&hist[j], pk);
        }
    }
}

__global__ void __launch_bounds__(MTHREADS) k_main(const float* __restrict__ A,
                                                   const float* __restrict__ B, int N) {
    __shared__ unsigned long long s_h[2 * 4 * 33];   // [term][copy*33+bin]
    __shared__ float s_sc[4][MTHREADS / 32];
    int t = threadIdx.x;
    for (int i = t; i < 264; i += MTHREADS) s_h[i] = 0ull;

    const float flo0 = g_p.f_lo[0], fhi0 = g_p.f_hi[0], mlo0 = g_p.m_lo[0], mhi0 = g_p.m_hi[0];
    const float pt0 = g_p.preterm[0], t00 = g_p.t0[0], is0 = g_p.invstep[0], st0 = g_p.step[0];
    const float flo1 = g_p.f_lo[1], fhi1 = g_p.f_hi[1], mlo1 = g_p.m_lo[1], mhi1 = g_p.m_hi[1];
    const float pt1 = g_p.preterm[1], t01 = g_p.t0[1], is1 = g_p.invstep[1], st1 = g_p.step[1];
    const float SW = g_p.sw_scale, SX0 = g_p.sx_scale[0], SX1 = g_p.sx_scale[1];
    __syncthreads();

    unsigned long long* h0 = &s_h[(t & 3) * 33];
    unsigned long long* h1 = &s_h[132 + (t & 3) * 33];

    const float4* A4 = (const float4*)A;
    const float4* B4 = (const float4*)B;
    int N4 = N >> 2;
    int stride = gridDim.x * MTHREADS;
    float sx0 = 0.f, sxx0 = 0.f, sx1 = 0.f, sxx1 = 0.f;

    for (int i = blockIdx.x * MTHREADS + t; i < N4; i += stride) {
        float4 va = A4[i], vb = B4[i];
        float ea[4] = {va.x, va.y, va.z, va.w};
        float eb[4] = {vb.x, vb.y, vb.z, vb.w};
        #pragma unroll
        for (int e = 0; e < 4; e++) {
            float a = ea[e], b = eb[e];
            // term 0: target = B, pred = A
            float y = fminf(fmaxf(b, flo0), fhi0);
            float x = fminf(fmaxf(a, mlo0), mhi0);
            sx0 += x; sxx0 += x * x;
            accum5(y, x, pt0, t00, is0, st0, SW, SX0, h0);
            // term 1: target = A, pred = B
            y = fminf(fmaxf(a, flo1), fhi1);
            x = fminf(fmaxf(b, mlo1), mhi1);
            sx1 += x; sxx1 += x * x;
            accum5(y, x, pt1, t01, is1, st1, SW, SX1, h1);
        }
    }
    // scalar tail (block 0, thread 0)
    if (blockIdx.x == 0 && t == 0) {
        for (int r = N4 << 2; r < N; r++) {
            float a = A[r], b = B[r];
            float y = fminf(fmaxf(b, flo0), fhi0);
            float x = fminf(fmaxf(a, mlo0), mhi0);
            sx0 += x; sxx0 += x * x;
            accum5(y, x, pt0, t00, is0, st0, SW, SX0, h0);
            y = fminf(fmaxf(a, flo1), fhi1);
            x = fminf(fmaxf(b, mlo1), mhi1);
            sx1 += x; sxx1 += x * x;
            accum5(y, x, pt1, t01, is1, st1, SW, SX1, h1);
        }
    }

    // deterministic scalar reduce: shfl (fixed order) then warp leaders
    int lane = t & 31, warp = t >> 5;
    #pragma unroll
    for (int off = 16; off; off >>= 1) {
        sx0  += __shfl_down_sync(0xFFFFFFFFu, sx0,  off);
        sxx0 += __shfl_down_sync(0xFFFFFFFFu, sxx0, off);
        sx1  += __shfl_down_sync(0xFFFFFFFFu, sx1,  off);
        sxx1 += __shfl_down_sync(0xFFFFFFFFu, sxx1, off);
    }
    if (lane == 0) {
        s_sc[0][warp] = sx0; s_sc[1][warp] = sxx0;
        s_sc[2][warp] = sx1; s_sc[3][warp] = sxx1;
    }
    __syncthreads();

    int blk = blockIdx.x;
    if (t < 64) {
        int term = t >> 5, bin = t & 31;
        unsigned long long tot = 0ull;
        #pragma unroll
        for (int c = 0; c < 4; c++) tot += s_h[term * 132 + c * 33 + bin];
        unsigned hi = (unsigned)(tot >> 32);
        int lo = (int)(unsigned)(tot & 0xFFFFFFFFull);
        unsigned hwT = hi + ((lo < 0) ? 1u : 0u);   // undo borrow
        g_hw[(term * 32 + bin) * MGRID + blk] = hwT;
        g_lw[(term * 32 + bin) * MGRID + blk] = lo;
    }
    if (t < 4) {
        float s = 0.f;
        #pragma unroll
        for (int w = 0; w < MTHREADS / 32; w++) s += s_sc[t][w];
        g_sc[t * MGRID + blk] = s;
    }
}

// ---------------- exact final reduction + scalar math ----------------
__global__ void k_final(float* __restrict__ out, int N) {
    __shared__ long long sH[64][8], sL[64][8];
    __shared__ double sS[4][8];
    __shared__ long long totH[64], totL[64];
    __shared__ double totS[4];
    int t = threadIdx.x;
    int slot = t >> 3, sub = t & 7;
    if (slot < 64) {
        long long aH = 0, aL = 0;
        const unsigned* ph = &g_hw[slot * MGRID];
        const int* pl = &g_lw[slot * MGRID];
        for (int b = sub; b < MGRID; b += 8) { aH += (long long)ph[b]; aL += (long long)pl[b]; }
        sH[slot][sub] = aH; sL[slot][sub] = aL;
    }
    if (t >= 512 && t < 512 + 32) {
        int sl = (t - 512) >> 3, sb = t & 7;
        double acc = 0.0;
        const float* p = &g_sc[sl * MGRID];
        for (int b = sb; b < MGRID; b += 8) acc += (double)p[b];
        sS[sl][sb] = acc;
    }
    __syncthreads();
    if (t < 64) {
        long long aH = 0, aL = 0;
        #pragma unroll
        for (int s = 0; s < 8; s++) { aH += sH[t][s]; aL += sL[t][s]; }
        totH[t] = aH; totL[t] = aL;
    }
    if (t >= 64 && t < 68) {
        int sl = t - 64; double a = 0.0;
        #pragma unroll
        for (int s = 0; s < 8; s++) a += sS[sl][s];
        totS[sl] = a;
    }
    __syncthreads();
    if (t == 0) {
        const double eps = 1.1920928955078125e-07;
        double dN = (double)N;
        double swi = (double)g_p.sw_inv;
        double eta = 0.0;
        for (int term = 0; term < 2; term++) {
            double sxi = (double)g_p.sx_inv[term];
            double sx = totS[2 * term], sxx = totS[2 * term + 1];
            double mean = sx / dN;
            double Ssw = 0.0, num = 0.0;
            for (int j = 0; j < NB; j++) {
                double sw = (double)totH[term * 32 + j] * swi;
                double swx = (double)totL[term * 32 + j] * sxi;
                double m = swx / (sw + eps);
                double d = m - mean;
                num += sw * d * d;
                Ssw += sw;
            }
            double bgv = num / (Ssw + eps);
            double var = (sxx - sx * sx / dN) / (dN - 1.0);
            eta += bgv / (var + eps);
        }
        out[0] = (float)(-0.5 * eta);
    }
}

extern "C" void kernel_launch(void* const* d_in, const int* in_sizes, int n_in,
                              void* d_out, int out_size) {
    const float* A = (const float*)d_in[0];
    const float* B = (const float*)d_in[1];
    int N = in_sizes[0];

    double n1 = (double)N - 1.0;
    double p01 = 0.01 * n1, p99 = 0.99 * n1;
    unsigned k01 = (unsigned)p01, k99 = (unsigned)p99;
    float f01 = (float)(p01 - (double)k01);
    float f99 = (float)(p99 - (double)k99);

    // max elements accumulated per k_main block (for fixed-point overflow bounds)
    int n4 = N >> 2;
    int iters = (n4 + MGRID * MTHREADS - 1) / (MGRID * MTHREADS);
    int epb = iters * 4 * MTHREADS + 4;   // + tail margin

    k_qinit<<<1, 256>>>(k01, k99);
    for (int pass = 0; pass < 4; pass++) {
        k_hist<<<HGRID, HTHREADS>>>(A, B, pass, N);
        k_scan<<<1, 256>>>(pass);
    }
    k_prep<<<1, 1>>>(f01, f99, epb);
    k_main<<<MGRID, MTHREADS>>>(A, B, N);
    k_final<<<1, 1024>>>((float*)d_out, N);
}

// round 5
// speedup vs baseline: 2.3001x; 1.0627x over previous
#include <cuda_runtime.h>
#include <math.h>

#define NB 32
static constexpr int HGRID   = 2048;
static constexpr int HTHREADS= 256;
static constexpr int MGRID   = 2048;
static constexpr int MTHREADS= 256;
static constexpr int NCOPY   = 8;     // k_main histogram replication
static constexpr int HSTRIDE = 40;    // 36 used (bins -2..33) + pad

// ---------------- radix-select state: 4 jobs per array (k01, k01+1, k99, k99+1) ----
struct QS {
    unsigned pref[2][4];
    unsigned rank[2][4];
    unsigned key[2][4];
};
__device__ QS g_qs;
__device__ int g_hist[2][4][256];   // [array][job][bin]

struct Params {
    float f_lo[2], f_hi[2], m_lo[2], m_hi[2];
    float t0[2], invstep[2];
    float cA2[2], cE2[2], Q[2], Q3[2];    // exp-recurrence constants (exp2 domain + linear)
    float sw_scale, sx_scale[2];
    float sw_inv, sx_inv[2];
};
__device__ Params g_p;

// per-block partials (exact integers for bins, fp32 for scalars)
__device__ unsigned g_hw[64 * MGRID];
__device__ int      g_lw[64 * MGRID];
__device__ float    g_sc[4 * MGRID];

__device__ __forceinline__ unsigned f2key(float f) {
    unsigned u = __float_as_uint(f);
    return (u & 0x80000000u) ? ~u : (u | 0x80000000u);
}
__device__ __forceinline__ float key2f(unsigned k) {
    unsigned u = (k & 0x80000000u) ? (k & 0x7FFFFFFFu) : ~k;
    return __uint_as_float(u);
}

// fused histogram: both arrays, all jobs, float4 loads; pass0 also inits QS
__global__ void __launch_bounds__(HTHREADS) k_hist(const float* __restrict__ A,
                                                   const float* __restrict__ B,
                                                   int pass, int N,
                                                   unsigned k01, unsigned k99) {
    __shared__ int sh[8][256];
    int t = threadIdx.x;
    for (int i = t; i < 2048; i += HTHREADS) (&sh[0][0])[i] = 0;
    if (pass == 0 && blockIdx.x == 0 && t < 8) {
        int a = t >> 2, j = t & 3;
        g_qs.pref[a][j] = 0u;
        g_qs.rank[a][j] = (j < 2 ? k01 : k99) + (unsigned)(j & 1);
    }
    __syncthreads();

    const float4* A4 = (const float4*)A;
    const float4* B4 = (const float4*)B;
    int N4 = N >> 2;
    int stride = gridDim.x * HTHREADS;
    int i0 = blockIdx.x * HTHREADS + t;

    if (pass == 0) {
        int ca = (t & 3), cb = 4 + (t & 3);
        for (int i = i0; i < N4; i += stride) {
            float4 va = A4[i], vb = B4[i];
            atomicAdd(&sh[ca][f2key(va.x) >> 24], 1);
            atomicAdd(&sh[ca][f2key(va.y) >> 24], 1);
            atomicAdd(&sh[ca][f2key(va.z) >> 24], 1);
            atomicAdd(&sh[ca][f2key(va.w) >> 24], 1);
            atomicAdd(&sh[cb][f2key(vb.x) >> 24], 1);
            atomicAdd(&sh[cb][f2key(vb.y) >> 24], 1);
            atomicAdd(&sh[cb][f2key(vb.z) >> 24], 1);
            atomicAdd(&sh[cb][f2key(vb.w) >> 24], 1);
        }
        if (i0 == 0) {
            for (int r = N4 << 2; r < N; r++) {
                atomicAdd(&sh[0][f2key(A[r]) >> 24], 1);
                atomicAdd(&sh[4][f2key(B[r]) >> 24], 1);
            }
        }
    } else {
        unsigned pa[4], pb[4];
        #pragma unroll
        for (int j = 0; j < 4; j++) { pa[j] = g_qs.pref[0][j]; pb[j] = g_qs.pref[1][j]; }
        int ms = 32 - 8 * pass, bs = 24 - 8 * pass;
        for (int i = i0; i < N4; i += stride) {
            float4 va = A4[i], vb = B4[i];
            float ea[4] = {va.x, va.y, va.z, va.w};
            float eb[4] = {vb.x, vb.y, vb.z, vb.w};
            #pragma unroll
            for (int e = 0; e < 4; e++) {
                unsigned k = f2key(ea[e]);
                unsigned top = k >> ms, b = (k >> bs) & 255u;
                #pragma unroll
                for (int j = 0; j < 4; j++)
                    if (top == pa[j]) atomicAdd(&sh[j][b], 1);
                k = f2key(eb[e]);
                top = k >> ms; b = (k >> bs) & 255u;
                #pragma unroll
                for (int j = 0; j < 4; j++)
                    if (top == pb[j]) atomicAdd(&sh[4 + j][b], 1);
            }
        }
        if (i0 == 0) {
            for (int r = N4 << 2; r < N; r++) {
                unsigned k = f2key(A[r]);
                unsigned top = k >> ms, b = (k >> bs) & 255u;
                for (int j = 0; j < 4; j++) if (top == pa[j]) atomicAdd(&sh[j][b], 1);
                k = f2key(B[r]); top = k >> ms; b = (k >> bs) & 255u;
                for (int j = 0; j < 4; j++) if (top == pb[j]) atomicAdd(&sh[4 + j][b], 1);
            }
        }
    }
    __syncthreads();
    for (int i = t; i < 2048; i += HTHREADS) {
        int v = (&sh[0][0])[i];
        if (v) {
            int row = i >> 8, bin = i & 255;
            int a = row >> 2;
            int j = (pass == 0) ? 0 : (row & 3);
            atomicAdd(&g_hist[a][j][bin], v);
        }
    }
}

// parallel scan; on pass 3 also computes all Params (fused former k_prep)
__global__ void k_scan(int pass, float frac01, float frac99, int epb) {
    int t = threadIdx.x, warp = t >> 5, lane = t & 31;
    if (warp < 8) {
        int a = warp >> 2, jj = warp & 3;
        int jsel = (pass == 0) ? 0 : jj;
        const int* h = &g_hist[a][jsel][0];
        int c[8]; int ps = 0;
        #pragma unroll
        for (int k = 0; k < 8; k++) { c[k] = h[lane * 8 + k]; ps += c[k]; }
        int v = ps;
        #pragma unroll
        for (int off = 1; off < 32; off <<= 1) {
            int n = __shfl_up_sync(0xFFFFFFFFu, v, off);
            if (lane >= off) v += n;
        }
        unsigned excl = (unsigned)(v - ps);
        unsigned rank = g_qs.rank[a][jj];
        bool has = (rank >= excl) && (rank < excl + (unsigned)ps);
        if (has) {
            unsigned cum = excl; int d = 0;
            #pragma unroll
            for (int k = 0; k < 8; k++) {
                if (cum + (unsigned)c[k] > rank) { d = k; break; }
                cum += (unsigned)c[k];
            }
            unsigned np = (g_qs.pref[a][jj] << 8) | (unsigned)(lane * 8 + d);
            g_qs.pref[a][jj] = np;
            g_qs.rank[a][jj] = rank - cum;
            if (pass == 3) g_qs.key[a][jj] = np;
        }
    }
    __syncthreads();
    int* h = &g_hist[0][0][0];
    for (int i = t; i < 2048; i += blockDim.x) h[i] = 0;

    if (pass == 3 && t == 0) {
        float q[2][2];
        for (int a = 0; a < 2; a++) {
            float v0 = key2f(g_qs.key[a][0]), v1 = key2f(g_qs.key[a][1]);
            q[a][0] = v0 + frac01 * (v1 - v0);
            v0 = key2f(g_qs.key[a][2]); v1 = key2f(g_qs.key[a][3]);
            q[a][1] = v0 + frac99 * (v1 - v0);
        }
        const float sigma_ratio = (float)(1.0 / 2.355);
        for (int term = 0; term < 2; term++) {
            int pa = term, ta = 1 - term;
            float flo = q[ta][0], fhi = q[ta][1];
            g_p.f_lo[term] = flo; g_p.f_hi[term] = fhi;
            g_p.m_lo[term] = q[pa][0]; g_p.m_hi[term] = q[pa][1];
            float fb = (fhi - flo) / (float)NB;
            float lo = flo + 0.5f * fb;
            float hi = fhi - 0.5f * fb;
            float step = (hi - lo) / (float)(NB - 1);
            // mean(diff(linspace)) exactly as reference (f32)
            float sd = 0.0f, prev = lo;
            for (int i = 1; i < NB; i++) {
                float v = lo + step * (float)i;
                sd += (v - prev); prev = v;
            }
            float fs = (sd / (float)(NB - 1)) * sigma_ratio;
            float preterm = 1.0f / (2.0f * fs * fs);
            g_p.t0[term] = lo;
            g_p.invstep[term] = 1.0f / step;
            float cA = preterm * step * step;
            g_p.cA2[term] = cA * 1.4426950408889634f;
            g_p.cE2[term] = 2.0f * cA * 1.4426950408889634f;
            float Qv = __expf(-cA);
            g_p.Q[term] = Qv;
            g_p.Q3[term] = Qv * Qv * Qv;
            float xm = fmaxf(fabsf(g_p.m_lo[term]), fabsf(g_p.m_hi[term]));
            if (xm < 1e-20f) xm = 1e-20f;
            float sx = exp2f(floorf(log2f(1073741824.0f / ((float)epb * xm))));
            g_p.sx_scale[term] = sx;
            g_p.sx_inv[term] = 1.0f / sx;
        }
        float sw = exp2f(floorf(log2f(1073741824.0f / (float)epb)));
        g_p.sw_scale = sw;
        g_p.sw_inv = 1.0f / sw;
    }
}

// ---------------- main Parzen kernel: exp recurrence, branch-free padded bins ----
__device__ __forceinline__ unsigned long long pk(float w, float SW, float xs) {
    unsigned hw = __float2uint_rn(w * SW);
    int lw = __float2int_rn(w * xs);
    return ((unsigned long long)hw << 32) + (unsigned long long)(long long)lw;
}

__device__ __forceinline__ void accum5(float y, float x,
                                       float t0, float is,
                                       float cA2, float cE2, float Qc, float Q3c,
                                       float SW, float SX,
                                       unsigned long long* h) {
    float g = (y - t0) * is;
    int b0 = __float2int_rn(g);
    b0 = min(max(b0, 0), NB - 1);
    float un = g - (float)b0;                 // in [-0.5, 0.5]
    float z = cE2 * un;
    float A  = exp2f(-cA2 * un * un);
    float E  = exp2f(z);
    float Ei = exp2f(-z);
    float EQ = E * Qc, EiQ = Ei * Qc;
    float wp1 = A * EQ,  wp2 = wp1 * (E * Q3c);
    float wm1 = A * EiQ, wm2 = wm1 * (Ei * Q3c);
    float xs = x * SX;
    unsigned long long* hb = h + (b0 + 2);    // pad offset: bins -2..33 valid
    atomicAdd(&hb[-2], pk(wm2, SW, xs));
    atomicAdd(&hb[-1], pk(wm1, SW, xs));
    atomicAdd(&hb[ 0], pk(A,   SW, xs));
    atomicAdd(&hb[ 1], pk(wp1, SW, xs));
    atomicAdd(&hb[ 2], pk(wp2, SW, xs));
}

__global__ void __launch_bounds__(MTHREADS) k_main(const float* __restrict__ A,
                                                   const float* __restrict__ B, int N) {
    __shared__ unsigned long long s_h[2 * NCOPY * HSTRIDE];
    __shared__ float s_sc[4][MTHREADS / 32];
    int t = threadIdx.x;
    for (int i = t; i < 2 * NCOPY * HSTRIDE; i += MTHREADS) s_h[i] = 0ull;

    const float flo0 = g_p.f_lo[0], fhi0 = g_p.f_hi[0], mlo0 = g_p.m_lo[0], mhi0 = g_p.m_hi[0];
    const float t00 = g_p.t0[0], is0 = g_p.invstep[0];
    const float cA20 = g_p.cA2[0], cE20 = g_p.cE2[0], Q0 = g_p.Q[0], Q30 = g_p.Q3[0];
    const float flo1 = g_p.f_lo[1], fhi1 = g_p.f_hi[1], mlo1 = g_p.m_lo[1], mhi1 = g_p.m_hi[1];
    const float t01 = g_p.t0[1], is1 = g_p.invstep[1];
    const float cA21 = g_p.cA2[1], cE21 = g_p.cE2[1], Q1 = g_p.Q[1], Q31 = g_p.Q3[1];
    const float SW = g_p.sw_scale, SX0 = g_p.sx_scale[0], SX1 = g_p.sx_scale[1];
    __syncthreads();

    int cp = t & (NCOPY - 1);
    unsigned long long* h0 = &s_h[cp * HSTRIDE];
    unsigned long long* h1 = &s_h[NCOPY * HSTRIDE + cp * HSTRIDE];

    const float4* A4 = (const float4*)A;
    const float4* B4 = (const float4*)B;
    int N4 = N >> 2;
    int stride = gridDim.x * MTHREADS;
    float sx0 = 0.f, sxx0 = 0.f, sx1 = 0.f, sxx1 = 0.f;

    for (int i = blockIdx.x * MTHREADS + t; i < N4; i += stride) {
        float4 va = A4[i], vb = B4[i];
        float ea[4] = {va.x, va.y, va.z, va.w};
        float eb[4] = {vb.x, vb.y, vb.z, vb.w};
        #pragma unroll
        for (int e = 0; e < 4; e++) {
            float a = ea[e], b = eb[e];
            float y = fminf(fmaxf(b, flo0), fhi0);
            float x = fminf(fmaxf(a, mlo0), mhi0);
            sx0 += x; sxx0 += x * x;
            accum5(y, x, t00, is0, cA20, cE20, Q0, Q30, SW, SX0, h0);
            y = fminf(fmaxf(a, flo1), fhi1);
            x = fminf(fmaxf(b, mlo1), mhi1);
            sx1 += x; sxx1 += x * x;
            accum5(y, x, t01, is1, cA21, cE21, Q1, Q31, SW, SX1, h1);
        }
    }
    if (blockIdx.x == 0 && t == 0) {
        for (int r = N4 << 2; r < N; r++) {
            float a = A[r], b = B[r];
            float y = fminf(fmaxf(b, flo0), fhi0);
            float x = fminf(fmaxf(a, mlo0), mhi0);
            sx0 += x; sxx0 += x * x;
            accum5(y, x, t00, is0, cA20, cE20, Q0, Q30, SW, SX0, h0);
            y = fminf(fmaxf(a, flo1), fhi1);
            x = fminf(fmaxf(b, mlo1), mhi1);
            sx1 += x; sxx1 += x * x;
            accum5(y, x, t01, is1, cA21, cE21, Q1, Q31, SW, SX1, h1);
        }
    }

    int lane = t & 31, warp = t >> 5;
    #pragma unroll
    for (int off = 16; off; off >>= 1) {
        sx0  += __shfl_down_sync(0xFFFFFFFFu, sx0,  off);
        sxx0 += __shfl_down_sync(0xFFFFFFFFu, sxx0, off);
        sx1  += __shfl_down_sync(0xFFFFFFFFu, sx1,  off);
        sxx1 += __shfl_down_sync(0xFFFFFFFFu, sxx1, off);
    }
    if (lane == 0) {
        s_sc[0][warp] = sx0; s_sc[1][warp] = sxx0;
        s_sc[2][warp] = sx1; s_sc[3][warp] = sxx1;
    }
    __syncthreads();

    int blk = blockIdx.x;
    if (t < 64) {
        int term = t >> 5, bin = t & 31;
        unsigned long long tot = 0ull;
        #pragma unroll
        for (int c = 0; c < NCOPY; c++)
            tot += s_h[term * (NCOPY * HSTRIDE) + c * HSTRIDE + bin + 2];
        unsigned hi = (unsigned)(tot >> 32);
        int lo = (int)(unsigned)(tot & 0xFFFFFFFFull);
        unsigned hwT = hi + ((lo < 0) ? 1u : 0u);
        g_hw[(term * 32 + bin) * MGRID + blk] = hwT;
        g_lw[(term * 32 + bin) * MGRID + blk] = lo;
    }
    if (t < 4) {
        float s = 0.f;
        #pragma unroll
        for (int w = 0; w < MTHREADS / 32; w++) s += s_sc[t][w];
        g_sc[t * MGRID + blk] = s;
    }
}

// ---------------- exact final reduction + scalar math ----------------
__global__ void k_final(float* __restrict__ out, int N) {
    __shared__ long long sH[64][8], sL[64][8];
    __shared__ double sS[4][8];
    __shared__ long long totH[64], totL[64];
    __shared__ double totS[4];
    int t = threadIdx.x;
    int slot = t >> 3, sub = t & 7;
    if (slot < 64) {
        long long aH = 0, aL = 0;
        const unsigned* ph = &g_hw[slot * MGRID];
        const int* pl = &g_lw[slot * MGRID];
        for (int b = sub; b < MGRID; b += 8) { aH += (long long)ph[b]; aL += (long long)pl[b]; }
        sH[slot][sub] = aH; sL[slot][sub] = aL;
    }
    if (t >= 512 && t < 512 + 32) {
        int sl = (t - 512) >> 3, sb = t & 7;
        double acc = 0.0;
        const float* p = &g_sc[sl * MGRID];
        for (int b = sb; b < MGRID; b += 8) acc += (double)p[b];
        sS[sl][sb] = acc;
    }
    __syncthreads();
    if (t < 64) {
        long long aH = 0, aL = 0;
        #pragma unroll
        for (int s = 0; s < 8; s++) { aH += sH[t][s]; aL += sL[t][s]; }
        totH[t] = aH; totL[t] = aL;
    }
    if (t >= 64 && t < 68) {
        int sl = t - 64; double a = 0.0;
        #pragma unroll
        for (int s = 0; s < 8; s++) a += sS[sl][s];
        totS[sl] = a;
    }
    __syncthreads();
    if (t == 0) {
        const double eps = 1.1920928955078125e-07;
        double dN = (double)N;
        double swi = (double)g_p.sw_inv;
        double eta = 0.0;
        for (int term = 0; term < 2; term++) {
            double sxi = (double)g_p.sx_inv[term];
            double sx = totS[2 * term], sxx = totS[2 * term + 1];
            double mean = sx / dN;
            double Ssw = 0.0, num = 0.0;
            for (int j = 0; j < NB; j++) {
                double sw = (double)totH[term * 32 + j] * swi;
                double swx = (double)totL[term * 32 + j] * sxi;
                double m = swx / (sw + eps);
                double d = m - mean;
                num += sw * d * d;
                Ssw += sw;
            }
            double bgv = num / (Ssw + eps);
            double var = (sxx - sx * sx / dN) / (dN - 1.0);
            eta += bgv / (var + eps);
        }
        out[0] = (float)(-0.5 * eta);
    }
}

extern "C" void kernel_launch(void* const* d_in, const int* in_sizes, int n_in,
                              void* d_out, int out_size) {
    const float* A = (const float*)d_in[0];
    const float* B = (const float*)d_in[1];
    int N = in_sizes[0];

    double n1 = (double)N - 1.0;
    double p01 = 0.01 * n1, p99 = 0.99 * n1;
    unsigned k01 = (unsigned)p01, k99 = (unsigned)p99;
    float f01 = (float)(p01 - (double)k01);
    float f99 = (float)(p99 - (double)k99);

    int n4 = N >> 2;
    int iters = (n4 + MGRID * MTHREADS - 1) / (MGRID * MTHREADS);
    int epb = iters * 4 * MTHREADS + 4;

    for (int pass = 0; pass < 4; pass++) {
        k_hist<<<HGRID, HTHREADS>>>(A, B, pass, N, k01, k99);
        k_scan<<<1, 256>>>(pass, f01, f99, epb);
    }
    k_main<<<MGRID, MTHREADS>>>(A, B, N);
    k_final<<<1, 1024>>>((float*)d_out, N);
}

// round 6
// speedup vs baseline: 2.8637x; 1.2450x over previous
#include <cuda_runtime.h>
#include <math.h>

#define NB 32
static constexpr int TPB    = 128;
static constexpr int MAXB   = 1024;
static constexpr int NSLOT2 = 72;                    // 2 terms * 36 padded bins
static constexpr int SMEM_BYTES = NSLOT2 * TPB * 8;  // 73728

// ---------------- radix-select state ----------------
struct QS { unsigned pref[2][4]; unsigned rank[2][4]; unsigned key[2][4]; };
__device__ QS g_qs;
__device__ int g_hist[2][4][256];

struct TermP {
    float flo, fhi, mlo, mhi, t0, is, Qc, Q4c, SX, SXinv;
    float ac[10];   // e^{-c s} coeffs (s = un^2)
    float cc[9];    // cosh(2c un) coeffs in s
    float sc[8];    // sinh(2c un)/un coeffs in s (2c folded in)
};
struct Params { TermP tp[2]; float SW, SWinv; };
__device__ Params g_p;

__device__ unsigned long long g_bH[MAXB * NSLOT2];
__device__ long long          g_bL[MAXB * NSLOT2];
__device__ double             g_bsc[MAXB * 4];

// ---------------- grid barrier (sense reversing) ----------------
__device__ unsigned g_arrive = 0;
__device__ unsigned g_gen = 0;

__device__ __forceinline__ void gridbar() {
    __threadfence();
    __syncthreads();
    if (threadIdx.x == 0) {
        unsigned gen = *(volatile unsigned*)&g_gen;
        unsigned prev = atomicAdd(&g_arrive, 1u);
        if (prev == gridDim.x - 1u) {
            g_arrive = 0u;
            __threadfence();
            *(volatile unsigned*)&g_gen = gen + 1u;
        } else {
            while (*(volatile unsigned*)&g_gen == gen) __nanosleep(64);
        }
        __threadfence();
    }
    __syncthreads();
}

__device__ __forceinline__ unsigned f2key(float f) {
    unsigned u = __float_as_uint(f);
    return (u & 0x80000000u) ? ~u : (u | 0x80000000u);
}
__device__ __forceinline__ float key2f(unsigned k) {
    unsigned u = (k & 0x80000000u) ? (k & 0x7FFFFFFFu) : ~k;
    return __uint_as_float(u);
}

__device__ __forceinline__ unsigned long long pack2(float w, float SW, float xs) {
    unsigned hw = __float2uint_rn(w * SW);
    int lw = __float2int_rn(w * xs);
    return ((unsigned long long)hw << 32) + (unsigned long long)(long long)lw;
}

// per-(element,term) Parzen update into private histogram column
__device__ __forceinline__ void accum(const TermP& tc, float yraw, float xraw,
                                      float SW, unsigned long long* base,
                                      float& sx, float& sxx) {
    float y = fminf(fmaxf(yraw, tc.flo), tc.fhi);
    float x = fminf(fmaxf(xraw, tc.mlo), tc.mhi);
    sx += x; sxx += x * x;
    float g = (y - tc.t0) * tc.is;
    int b0 = __float2int_rn(g);
    b0 = min(max(b0, 0), NB - 1);
    float un = g - (float)b0;          // in [-0.5, 0.5]
    float s = un * un;
    float Ap = tc.ac[9];
    #pragma unroll
    for (int k = 8; k >= 0; k--) Ap = fmaf(Ap, s, tc.ac[k]);
    float C = tc.cc[8];
    #pragma unroll
    for (int k = 7; k >= 0; k--) C = fmaf(C, s, tc.cc[k]);
    float Sp = tc.sc[7];
    #pragma unroll
    for (int k = 6; k >= 0; k--) Sp = fmaf(Sp, s, tc.sc[k]);
    float S = Sp * un;
    float E = C + S, Ei = C - S;       // e^{2c un}, e^{-2c un}
    float AQ = Ap * tc.Qc, AQ4 = Ap * tc.Q4c;
    float w1p = AQ * E, w1m = AQ * Ei;
    float w2p = AQ4 * (E * E), w2m = AQ4 * (Ei * Ei);
    float xs = x * tc.SX;
    unsigned long long* p = base + (unsigned)b0 * (unsigned)TPB;
    p[-2 * TPB] = p[-2 * TPB] + pack2(w2m, SW, xs);
    p[-1 * TPB] = p[-1 * TPB] + pack2(w1m, SW, xs);
    p[0]        = p[0]        + pack2(Ap,  SW, xs);
    p[1 * TPB]  = p[1 * TPB]  + pack2(w1p, SW, xs);
    p[2 * TPB]  = p[2 * TPB]  + pack2(w2p, SW, xs);
}

__global__ void __launch_bounds__(TPB, 3)
k_fused(const float* __restrict__ A, const float* __restrict__ B, int N,
        unsigned k01, unsigned k99, float f01, float f99, int epb,
        float* __restrict__ out)
{
    extern __shared__ unsigned long long dyn[];
    unsigned long long* priv = dyn;
    int* shist = (int*)dyn;
    __shared__ float s_sc[4][TPB / 32];
    __shared__ unsigned long long s_H[NSLOT2];
    __shared__ long long s_L[NSLOT2];
    __shared__ double s_fin[4];

    int t = threadIdx.x;
    int nb = gridDim.x;
    int gsz = nb * TPB;
    int gid = blockIdx.x * TPB + t;
    const float4* A4 = (const float4*)A;
    const float4* B4 = (const float4*)B;
    int N4 = N >> 2;

    if (blockIdx.x == 0 && t < 8) {
        int a = t >> 2, j = t & 3;
        g_qs.pref[a][j] = 0u;
        g_qs.rank[a][j] = (j < 2 ? k01 : k99) + (unsigned)(j & 1);
    }

    // ================= quantile phase: 4 radix passes =================
    for (int pass = 0; pass < 4; pass++) {
        for (int i = t; i < 2048; i += TPB) shist[i] = 0;
        __syncthreads();
        if (pass == 0) {
            int ca = (t & 3) * 256, cb = (4 + (t & 3)) * 256;
            for (int i = gid; i < N4; i += gsz) {
                float4 va = A4[i], vb = B4[i];
                atomicAdd(&shist[ca + (f2key(va.x) >> 24)], 1);
                atomicAdd(&shist[ca + (f2key(va.y) >> 24)], 1);
                atomicAdd(&shist[ca + (f2key(va.z) >> 24)], 1);
                atomicAdd(&shist[ca + (f2key(va.w) >> 24)], 1);
                atomicAdd(&shist[cb + (f2key(vb.x) >> 24)], 1);
                atomicAdd(&shist[cb + (f2key(vb.y) >> 24)], 1);
                atomicAdd(&shist[cb + (f2key(vb.z) >> 24)], 1);
                atomicAdd(&shist[cb + (f2key(vb.w) >> 24)], 1);
            }
            if (gid == 0) {
                for (int r = N4 << 2; r < N; r++) {
                    atomicAdd(&shist[0 * 256 + (f2key(A[r]) >> 24)], 1);
                    atomicAdd(&shist[4 * 256 + (f2key(B[r]) >> 24)], 1);
                }
            }
        } else {
            unsigned pa[4], pb[4];
            #pragma unroll
            for (int j = 0; j < 4; j++) { pa[j] = g_qs.pref[0][j]; pb[j] = g_qs.pref[1][j]; }
            int ms = 32 - 8 * pass, bs = 24 - 8 * pass;
            for (int i = gid; i < N4; i += gsz) {
                float4 va = A4[i], vb = B4[i];
                float ea[4] = {va.x, va.y, va.z, va.w};
                float eb[4] = {vb.x, vb.y, vb.z, vb.w};
                #pragma unroll
                for (int e = 0; e < 4; e++) {
                    unsigned k = f2key(ea[e]);
                    unsigned top = k >> ms, b = (k >> bs) & 255u;
                    #pragma unroll
                    for (int j = 0; j < 4; j++)
                        if (top == pa[j]) atomicAdd(&shist[j * 256 + b], 1);
                    k = f2key(eb[e]);
                    top = k >> ms; b = (k >> bs) & 255u;
                    #pragma unroll
                    for (int j = 0; j < 4; j++)
                        if (top == pb[j]) atomicAdd(&shist[(4 + j) * 256 + b], 1);
                }
            }
            if (gid == 0) {
                for (int r = N4 << 2; r < N; r++) {
                    unsigned k = f2key(A[r]);
                    unsigned top = k >> ms, b = (k >> bs) & 255u;
                    for (int j = 0; j < 4; j++) if (top == pa[j]) atomicAdd(&shist[j * 256 + b], 1);
                    k = f2key(B[r]); top = k >> ms; b = (k >> bs) & 255u;
                    for (int j = 0; j < 4; j++) if (top == pb[j]) atomicAdd(&shist[(4 + j) * 256 + b], 1);
                }
            }
        }
        __syncthreads();
        for (int i = t; i < 2048; i += TPB) {
            int v = shist[i];
            if (v) {
                int row = i >> 8, bin = i & 255;
                int a = row >> 2;
                int j = (pass == 0) ? 0 : (row & 3);
                atomicAdd(&g_hist[a][j][bin], v);
            }
        }
        gridbar();

        if (blockIdx.x == 0) {
            int warp = t >> 5, lane = t & 31;
            for (int q = warp; q < 8; q += 4) {
                int a = q >> 2, jj = q & 3;
                int jsel = (pass == 0) ? 0 : jj;
                const int* h = &g_hist[a][jsel][0];
                int c[8]; int ps = 0;
                #pragma unroll
                for (int k = 0; k < 8; k++) { c[k] = h[lane * 8 + k]; ps += c[k]; }
                int v = ps;
                #pragma unroll
                for (int off = 1; off < 32; off <<= 1) {
                    int n = __shfl_up_sync(0xFFFFFFFFu, v, off);
                    if (lane >= off) v += n;
                }
                unsigned excl = (unsigned)(v - ps);
                unsigned rank = g_qs.rank[a][jj];
                bool has = (rank >= excl) && (rank < excl + (unsigned)ps);
                if (has) {
                    unsigned cum = excl; int d = 0;
                    #pragma unroll
                    for (int k = 0; k < 8; k++) {
                        if (cum + (unsigned)c[k] > rank) { d = k; break; }
                        cum += (unsigned)c[k];
                    }
                    unsigned np = (g_qs.pref[a][jj] << 8) | (unsigned)(lane * 8 + d);
                    g_qs.pref[a][jj] = np;
                    g_qs.rank[a][jj] = rank - cum;
                    if (pass == 3) g_qs.key[a][jj] = np;
                }
            }
            __syncthreads();
            for (int i = t; i < 2048; i += TPB) (&g_hist[0][0][0])[i] = 0;
            if (pass == 3 && t == 0) {
                // ---- params (fp32 mirroring reference, fp64 for poly coeffs) ----
                float q[2][2];
                for (int a = 0; a < 2; a++) {
                    float v0 = key2f(g_qs.key[a][0]), v1 = key2f(g_qs.key[a][1]);
                    q[a][0] = v0 + f01 * (v1 - v0);
                    v0 = key2f(g_qs.key[a][2]); v1 = key2f(g_qs.key[a][3]);
                    q[a][1] = v0 + f99 * (v1 - v0);
                }
                const float sigma_ratio = (float)(1.0 / 2.355);
                float swf = exp2f(floorf(log2f(1073741824.0f / (float)epb)));
                g_p.SW = swf; g_p.SWinv = 1.0f / swf;
                for (int term = 0; term < 2; term++) {
                    TermP& tp = g_p.tp[term];
                    int pa2 = term, ta2 = 1 - term;
                    float flo = q[ta2][0], fhi = q[ta2][1];
                    tp.flo = flo; tp.fhi = fhi;
                    tp.mlo = q[pa2][0]; tp.mhi = q[pa2][1];
                    float fb = (fhi - flo) / (float)NB;
                    float lo = flo + 0.5f * fb, hi = fhi - 0.5f * fb;
                    float step = (hi - lo) / (float)(NB - 1);
                    float sd = 0.f, prev = lo;
                    for (int i = 1; i < NB; i++) { float v = lo + step * (float)i; sd += v - prev; prev = v; }
                    float fs = (sd / (float)(NB - 1)) * sigma_ratio;
                    float preterm = 1.0f / (2.0f * fs * fs);
                    tp.t0 = lo; tp.is = 1.0f / step;
                    double c = (double)preterm * (double)step * (double)step;
                    double a = 1.0; tp.ac[0] = 1.0f;
                    for (int k = 1; k <= 9; k++) { a *= (-c) / (double)k; tp.ac[k] = (float)a; }
                    double X = 4.0 * c * c;
                    double tm = 1.0; tp.cc[0] = 1.0f;
                    for (int m = 1; m <= 8; m++) { tm *= X / ((double)(2 * m - 1) * (double)(2 * m)); tp.cc[m] = (float)tm; }
                    double st = 2.0 * c; tp.sc[0] = (float)st;
                    for (int m = 1; m <= 7; m++) { st *= X / ((double)(2 * m) * (double)(2 * m + 1)); tp.sc[m] = (float)st; }
                    tp.Qc = (float)exp(-c); tp.Q4c = (float)exp(-4.0 * c);
                    float xm = fmaxf(fabsf(tp.mlo), fabsf(tp.mhi));
                    if (xm < 1e-20f) xm = 1e-20f;
                    float sxs = exp2f(floorf(log2f(1073741824.0f / ((float)epb * xm))));
                    tp.SX = sxs; tp.SXinv = 1.0f / sxs;
                }
            }
        }
        gridbar();
    }

    // ================= main Parzen phase: private histograms =================
    TermP tc0 = g_p.tp[0];
    TermP tc1 = g_p.tp[1];
    float SW = g_p.SW;

    #pragma unroll
    for (int s = 0; s < NSLOT2; s++) priv[s * TPB + t] = 0ull;
    __syncthreads();

    unsigned long long* base0 = priv + (0 * 36 + 2) * TPB + t;
    unsigned long long* base1 = priv + (1 * 36 + 2) * TPB + t;
    float sx0 = 0.f, sxx0 = 0.f, sx1 = 0.f, sxx1 = 0.f;

    for (int i = gid; i < N4; i += gsz) {
        float4 va = A4[i], vb = B4[i];
        accum(tc0, vb.x, va.x, SW, base0, sx0, sxx0);
        accum(tc1, va.x, vb.x, SW, base1, sx1, sxx1);
        accum(tc0, vb.y, va.y, SW, base0, sx0, sxx0);
        accum(tc1, va.y, vb.y, SW, base1, sx1, sxx1);
        accum(tc0, vb.z, va.z, SW, base0, sx0, sxx0);
        accum(tc1, va.z, vb.z, SW, base1, sx1, sxx1);
        accum(tc0, vb.w, va.w, SW, base0, sx0, sxx0);
        accum(tc1, va.w, vb.w, SW, base1, sx1, sxx1);
    }
    if (gid == 0) {
        for (int r = N4 << 2; r < N; r++) {
            float a = A[r], b = B[r];
            accum(tc0, b, a, SW, base0, sx0, sxx0);
            accum(tc1, a, b, SW, base1, sx1, sxx1);
        }
    }

    // deterministic scalar reduce
    int lane = t & 31, warp = t >> 5;
    #pragma unroll
    for (int off = 16; off; off >>= 1) {
        sx0  += __shfl_down_sync(0xFFFFFFFFu, sx0,  off);
        sxx0 += __shfl_down_sync(0xFFFFFFFFu, sxx0, off);
        sx1  += __shfl_down_sync(0xFFFFFFFFu, sx1,  off);
        sxx1 += __shfl_down_sync(0xFFFFFFFFu, sxx1, off);
    }
    if (lane == 0) {
        s_sc[0][warp] = sx0; s_sc[1][warp] = sxx0;
        s_sc[2][warp] = sx1; s_sc[3][warp] = sxx1;
    }
    __syncthreads();

    // per-block fold: decode per-thread packed sums, accumulate wide (exact)
    if (t < NSLOT2) {
        unsigned long long H = 0; long long L = 0;
        #pragma unroll 4
        for (int jj = 0; jj < TPB; jj++) {
            int j = (jj + t) & (TPB - 1);            // rotate to avoid bank conflicts
            unsigned long long v = priv[t * TPB + j];
            int lo = (int)(unsigned)v;
            unsigned hi = (unsigned)(v >> 32) + ((lo < 0) ? 1u : 0u);
            H += hi; L += lo;
        }
        g_bH[blockIdx.x * NSLOT2 + t] = H;
        g_bL[blockIdx.x * NSLOT2 + t] = L;
    }
    if (t < 4) {
        double s = 0.0;
        #pragma unroll
        for (int w = 0; w < TPB / 32; w++) s += (double)s_sc[t][w];
        g_bsc[blockIdx.x * 4 + t] = s;
    }
    gridbar();

    // ================= final reduction (block 0 only) =================
    if (blockIdx.x == 0) {
        if (t < NSLOT2) {
            unsigned long long H = 0; long long L = 0;
            for (int b = 0; b < nb; b++) {
                H += g_bH[b * NSLOT2 + t];
                L += g_bL[b * NSLOT2 + t];
            }
            s_H[t] = H; s_L[t] = L;
        }
        if (t >= NSLOT2 && t < NSLOT2 + 4) {
            int k = t - NSLOT2;
            double a = 0.0;
            for (int b = 0; b < nb; b++) a += g_bsc[b * 4 + k];
            s_fin[k] = a;
        }
        __syncthreads();
        if (t == 0) {
            const double eps = 1.1920928955078125e-07;
            double dN = (double)N;
            double swi = (double)g_p.SWinv;
            double eta = 0.0;
            for (int term = 0; term < 2; term++) {
                double sxi = (double)g_p.tp[term].SXinv;
                double sx = s_fin[2 * term], sxx = s_fin[2 * term + 1];
                double mean = sx / dN;
                double Ssw = 0.0, num = 0.0;
                for (int j = 0; j < NB; j++) {
                    double sw = (double)s_H[term * 36 + 2 + j] * swi;
                    double swx = (double)s_L[term * 36 + 2 + j] * sxi;
                    double m = swx / (sw + eps);
                    double d = m - mean;
                    num += sw * d * d;
                    Ssw += sw;
                }
                double bgv = num / (Ssw + eps);
                double var = (sxx - sx * sx / dN) / (dN - 1.0);
                eta += bgv / (var + eps);
            }
            out[0] = (float)(-0.5 * eta);
        }
    }
}

extern "C" void kernel_launch(void* const* d_in, const int* in_sizes, int n_in,
                              void* d_out, int out_size) {
    const float* A = (const float*)d_in[0];
    const float* B = (const float*)d_in[1];
    int N = in_sizes[0];

    double n1 = (double)N - 1.0;
    double p01 = 0.01 * n1, p99 = 0.99 * n1;
    unsigned k01 = (unsigned)p01, k99 = (unsigned)p99;
    float f01 = (float)(p01 - (double)k01);
    float f99 = (float)(p99 - (double)k99);

    cudaFuncSetAttribute(k_fused, cudaFuncAttributeMaxDynamicSharedMemorySize, SMEM_BYTES);
    int bpsm = 0, sms = 0;
    cudaOccupancyMaxActiveBlocksPerMultiprocessor(&bpsm, k_fused, TPB, SMEM_BYTES);
    cudaDeviceGetAttribute(&sms, cudaDevAttrMultiProcessorCount, 0);
    if (bpsm < 1) bpsm = 1;
    long long grid = (long long)bpsm * (long long)sms;
    if (grid > MAXB) grid = MAXB;

    int n4 = N >> 2;
    long long totalT = grid * TPB;
    int iters = (int)((n4 + totalT - 1) / totalT);
    int epb = iters * 4 + 8;

    k_fused<<<(int)grid, TPB, SMEM_BYTES>>>(A, B, N, k01, k99, f01, f99, epb, (float*)d_out);
}

// round 7
// speedup vs baseline: 3.5228x; 1.2301x over previous
#include <cuda_runtime.h>
#include <math.h>

#define NB 32
static constexpr int TPB   = 128;
static constexpr int MAXB  = 1024;
static constexpr int PSLOT = 36;                      // padded bins (-2..33) one term
static constexpr int SMEM_BYTES = PSLOT * TPB * 8;    // 36864

// ---------------- radix-select state ----------------
struct QS { unsigned pref[2][4]; unsigned rank[2][4]; unsigned key[2][4]; };
__device__ QS g_qs;
__device__ int g_hist[2][4][256];

struct TermP {
    float flo, fhi, mlo, mhi, t0, is, Qc, Q4c, SX;
    float ac[9], cc[7], sc[7];
    double SXinv, SSX, SSXX, SSXinv, SSXXinv;
};
struct Params { TermP tp[2]; float SW; double SWinv; };
__device__ Params g_p;

// exact global accumulators (integer atomics -> deterministic)
__device__ unsigned long long g_accH[64];
__device__ unsigned long long g_accL[64];
__device__ unsigned long long g_accS[4];

// ---------------- grid barrier (sense reversing) ----------------
__device__ unsigned g_arrive = 0;
__device__ unsigned g_gen = 0;

__device__ __forceinline__ void gridbar() {
    __threadfence();
    __syncthreads();
    if (threadIdx.x == 0) {
        unsigned gen = *(volatile unsigned*)&g_gen;
        unsigned prev = atomicAdd(&g_arrive, 1u);
        if (prev == gridDim.x - 1u) {
            g_arrive = 0u;
            __threadfence();
            *(volatile unsigned*)&g_gen = gen + 1u;
        } else {
            while (*(volatile unsigned*)&g_gen == gen) __nanosleep(64);
        }
        __threadfence();
    }
    __syncthreads();
}

__device__ __forceinline__ unsigned f2key(float f) {
    unsigned u = __float_as_uint(f);
    return (u & 0x80000000u) ? ~u : (u | 0x80000000u);
}
__device__ __forceinline__ float key2f(unsigned k) {
    unsigned u = (k & 0x80000000u) ? (k & 0x7FFFFFFFu) : ~k;
    return __uint_as_float(u);
}

__device__ __forceinline__ unsigned long long pack2(float w, float SW, float xs) {
    unsigned hw = __float2uint_rn(w * SW);
    int lw = __float2int_rn(w * xs);
    return ((unsigned long long)hw << 32) + (unsigned long long)(long long)lw;
}

// ---------------- one-term Parzen pass over all data ----------------
__device__ __forceinline__ void parzen_pass(
    const float4* __restrict__ Y4, const float4* __restrict__ X4,
    const float* __restrict__ Ys, const float* __restrict__ Xs,
    int term, int N, int N4, int gid, int gsz,
    unsigned long long* priv)
{
    __shared__ float s_red[2][TPB / 32];
    int t = threadIdx.x;
    // copy hot constants to registers (skip the doubles)
    const TermP* tg = &g_p.tp[term];
    float flo = tg->flo, fhi = tg->fhi, mlo = tg->mlo, mhi = tg->mhi;
    float t0 = tg->t0, is = tg->is, Qc = tg->Qc, Q4c = tg->Q4c, SX = tg->SX;
    float ac[9], cc[7], sc[7];
    #pragma unroll
    for (int k = 0; k < 9; k++) ac[k] = tg->ac[k];
    #pragma unroll
    for (int k = 0; k < 7; k++) { cc[k] = tg->cc[k]; sc[k] = tg->sc[k]; }
    float SW = g_p.SW;

    #pragma unroll
    for (int s = 0; s < PSLOT; s++) priv[s * TPB + t] = 0ull;
    __syncthreads();

    unsigned long long* base = priv + 2 * TPB + t;
    float sx = 0.f, sxx = 0.f;

    for (int i = gid; i < N4; i += gsz) {
        float4 y4 = Y4[i], x4 = X4[i];
        float ye[4] = {y4.x, y4.y, y4.z, y4.w};
        float xe[4] = {x4.x, x4.y, x4.z, x4.w};
        #pragma unroll
        for (int e = 0; e < 4; e++) {
            float y = fminf(fmaxf(ye[e], flo), fhi);
            float x = fminf(fmaxf(xe[e], mlo), mhi);
            sx += x; sxx += x * x;
            float g = (y - t0) * is;
            int b0 = __float2int_rn(g);
            b0 = min(max(b0, 0), NB - 1);
            float un = g - (float)b0;
            float s = un * un;
            float Ap = ac[8];
            #pragma unroll
            for (int k = 7; k >= 0; k--) Ap = fmaf(Ap, s, ac[k]);
            float C = cc[6];
            #pragma unroll
            for (int k = 5; k >= 0; k--) C = fmaf(C, s, cc[k]);
            float Sp = sc[6];
            #pragma unroll
            for (int k = 5; k >= 0; k--) Sp = fmaf(Sp, s, sc[k]);
            float S = Sp * un;
            float E = C + S, Ei = C - S;
            float AQ = Ap * Qc, AQ4 = Ap * Q4c;
            float w1p = AQ * E, w1m = AQ * Ei;
            float w2p = AQ4 * (E * E), w2m = AQ4 * (Ei * Ei);
            float xsv = x * SX;
            unsigned long long* p = base + (unsigned)b0 * (unsigned)TPB;
            p[-2 * TPB] = p[-2 * TPB] + pack2(w2m, SW, xsv);
            p[-1 * TPB] = p[-1 * TPB] + pack2(w1m, SW, xsv);
            p[0]        = p[0]        + pack2(Ap,  SW, xsv);
            p[1 * TPB]  = p[1 * TPB]  + pack2(w1p, SW, xsv);
            p[2 * TPB]  = p[2 * TPB]  + pack2(w2p, SW, xsv);
        }
    }
    if (gid == 0) {
        for (int r = N4 << 2; r < N; r++) {
            float y = fminf(fmaxf(Ys[r], flo), fhi);
            float x = fminf(fmaxf(Xs[r], mlo), mhi);
            sx += x; sxx += x * x;
            float g = (y - t0) * is;
            int b0 = __float2int_rn(g);
            b0 = min(max(b0, 0), NB - 1);
            float un = g - (float)b0;
            float s = un * un;
            float Ap = ac[8];
            for (int k = 7; k >= 0; k--) Ap = fmaf(Ap, s, ac[k]);
            float C = cc[6];
            for (int k = 5; k >= 0; k--) C = fmaf(C, s, cc[k]);
            float Sp = sc[6];
            for (int k = 5; k >= 0; k--) Sp = fmaf(Sp, s, sc[k]);
            float S = Sp * un;
            float E = C + S, Ei = C - S;
            float AQ = Ap * Qc, AQ4 = Ap * Q4c;
            float xsv = x * SX;
            unsigned long long* p = base + (unsigned)b0 * (unsigned)TPB;
            p[-2 * TPB] = p[-2 * TPB] + pack2(AQ4 * (Ei * Ei), SW, xsv);
            p[-1 * TPB] = p[-1 * TPB] + pack2(AQ * Ei, SW, xsv);
            p[0]        = p[0]        + pack2(Ap, SW, xsv);
            p[1 * TPB]  = p[1 * TPB]  + pack2(AQ * E, SW, xsv);
            p[2 * TPB]  = p[2 * TPB]  + pack2(AQ4 * (E * E), SW, xsv);
        }
    }

    int lane = t & 31, warp = t >> 5;
    #pragma unroll
    for (int off = 16; off; off >>= 1) {
        sx  += __shfl_down_sync(0xFFFFFFFFu, sx,  off);
        sxx += __shfl_down_sync(0xFFFFFFFFu, sxx, off);
    }
    if (lane == 0) { s_red[0][warp] = sx; s_red[1][warp] = sxx; }
    __syncthreads();   // orders priv writes + s_red

    if (t < NB) {
        unsigned long long H = 0; long long L = 0;
        #pragma unroll 4
        for (int jj = 0; jj < TPB; jj++) {
            int j = (jj + t) & (TPB - 1);
            unsigned long long v = priv[(t + 2) * TPB + j];
            int lo = (int)(unsigned)v;
            unsigned hi = (unsigned)(v >> 32) + ((lo < 0) ? 1u : 0u);
            H += hi; L += lo;
        }
        atomicAdd(&g_accH[term * NB + t], H);
        atomicAdd(&g_accL[term * NB + t], (unsigned long long)L);
    }
    if (t == 0) {
        double bsx = 0.0, bsxx = 0.0;
        #pragma unroll
        for (int w = 0; w < TPB / 32; w++) { bsx += (double)s_red[0][w]; bsxx += (double)s_red[1][w]; }
        long long v1 = __double2ll_rn(bsx * tg->SSX);
        long long v2 = __double2ll_rn(bsxx * tg->SSXX);
        atomicAdd(&g_accS[term * 2 + 0], (unsigned long long)v1);
        atomicAdd(&g_accS[term * 2 + 1], (unsigned long long)v2);
    }
    __syncthreads();   // protect priv before next pass re-zeroes
}

__global__ void __launch_bounds__(TPB, 6)
k_fused(const float* __restrict__ A, const float* __restrict__ B, int N,
        unsigned k01, unsigned k99, float f01, float f99, int epb,
        float* __restrict__ out)
{
    extern __shared__ unsigned long long dyn[];
    unsigned long long* priv = dyn;
    int* shist = (int*)dyn;

    int t = threadIdx.x;
    int nb = gridDim.x;
    int gsz = nb * TPB;
    int gid = blockIdx.x * TPB + t;
    const float4* A4 = (const float4*)A;
    const float4* B4 = (const float4*)B;
    int N4 = N >> 2;

    if (blockIdx.x == 0) {
        if (t < 8) {
            int a = t >> 2, j = t & 3;
            g_qs.pref[a][j] = 0u;
            g_qs.rank[a][j] = (j < 2 ? k01 : k99) + (unsigned)(j & 1);
        }
        for (int i = t; i < 64; i += TPB) { g_accH[i] = 0ull; g_accL[i] = 0ull; }
        if (t < 4) g_accS[t] = 0ull;
    }

    // ================= quantile phase: 4 radix passes =================
    for (int pass = 0; pass < 4; pass++) {
        for (int i = t; i < 2048; i += TPB) shist[i] = 0;
        __syncthreads();
        if (pass == 0) {
            int ca = (t & 3) * 256, cb = (4 + (t & 3)) * 256;
            for (int i = gid; i < N4; i += gsz) {
                float4 va = A4[i], vb = B4[i];
                atomicAdd(&shist[ca + (f2key(va.x) >> 24)], 1);
                atomicAdd(&shist[ca + (f2key(va.y) >> 24)], 1);
                atomicAdd(&shist[ca + (f2key(va.z) >> 24)], 1);
                atomicAdd(&shist[ca + (f2key(va.w) >> 24)], 1);
                atomicAdd(&shist[cb + (f2key(vb.x) >> 24)], 1);
                atomicAdd(&shist[cb + (f2key(vb.y) >> 24)], 1);
                atomicAdd(&shist[cb + (f2key(vb.z) >> 24)], 1);
                atomicAdd(&shist[cb + (f2key(vb.w) >> 24)], 1);
            }
            if (gid == 0) {
                for (int r = N4 << 2; r < N; r++) {
                    atomicAdd(&shist[0 * 256 + (f2key(A[r]) >> 24)], 1);
                    atomicAdd(&shist[4 * 256 + (f2key(B[r]) >> 24)], 1);
                }
            }
        } else {
            unsigned pa[4], pb[4];
            #pragma unroll
            for (int j = 0; j < 4; j++) { pa[j] = g_qs.pref[0][j]; pb[j] = g_qs.pref[1][j]; }
            int ms = 32 - 8 * pass, bs = 24 - 8 * pass;
            for (int i = gid; i < N4; i += gsz) {
                float4 va = A4[i], vb = B4[i];
                float ea[4] = {va.x, va.y, va.z, va.w};
                float eb[4] = {vb.x, vb.y, vb.z, vb.w};
                #pragma unroll
                for (int e = 0; e < 4; e++) {
                    unsigned k = f2key(ea[e]);
                    unsigned top = k >> ms, b = (k >> bs) & 255u;
                    #pragma unroll
                    for (int j = 0; j < 4; j++)
                        if (top == pa[j]) atomicAdd(&shist[j * 256 + b], 1);
                    k = f2key(eb[e]);
                    top = k >> ms; b = (k >> bs) & 255u;
                    #pragma unroll
                    for (int j = 0; j < 4; j++)
                        if (top == pb[j]) atomicAdd(&shist[(4 + j) * 256 + b], 1);
                }
            }
            if (gid == 0) {
                for (int r = N4 << 2; r < N; r++) {
                    unsigned k = f2key(A[r]);
                    unsigned top = k >> ms, b = (k >> bs) & 255u;
                    for (int j = 0; j < 4; j++) if (top == pa[j]) atomicAdd(&shist[j * 256 + b], 1);
                    k = f2key(B[r]); top = k >> ms; b = (k >> bs) & 255u;
                    for (int j = 0; j < 4; j++) if (top == pb[j]) atomicAdd(&shist[(4 + j) * 256 + b], 1);
                }
            }
        }
        __syncthreads();
        for (int i = t; i < 2048; i += TPB) {
            int v = shist[i];
            if (v) {
                int row = i >> 8, bin = i & 255;
                int a = row >> 2;
                int j = (pass == 0) ? 0 : (row & 3);
                atomicAdd(&g_hist[a][j][bin], v);
            }
        }
        gridbar();

        if (blockIdx.x == 0) {
            int warp = t >> 5, lane = t & 31;
            for (int q = warp; q < 8; q += 4) {
                int a = q >> 2, jj = q & 3;
                int jsel = (pass == 0) ? 0 : jj;
                const int* h = &g_hist[a][jsel][0];
                int c[8]; int ps = 0;
                #pragma unroll
                for (int k = 0; k < 8; k++) { c[k] = h[lane * 8 + k]; ps += c[k]; }
                int v = ps;
                #pragma unroll
                for (int off = 1; off < 32; off <<= 1) {
                    int n = __shfl_up_sync(0xFFFFFFFFu, v, off);
                    if (lane >= off) v += n;
                }
                unsigned excl = (unsigned)(v - ps);
                unsigned rank = g_qs.rank[a][jj];
                bool has = (rank >= excl) && (rank < excl + (unsigned)ps);
                if (has) {
                    unsigned cum = excl; int d = 0;
                    #pragma unroll
                    for (int k = 0; k < 8; k++) {
                        if (cum + (unsigned)c[k] > rank) { d = k; break; }
                        cum += (unsigned)c[k];
                    }
                    unsigned np = (g_qs.pref[a][jj] << 8) | (unsigned)(lane * 8 + d);
                    g_qs.pref[a][jj] = np;
                    g_qs.rank[a][jj] = rank - cum;
                    if (pass == 3) g_qs.key[a][jj] = np;
                }
            }
            __syncthreads();
            for (int i = t; i < 2048; i += TPB) (&g_hist[0][0][0])[i] = 0;
            if (pass == 3 && t == 0) {
                float q[2][2];
                for (int a = 0; a < 2; a++) {
                    float v0 = key2f(g_qs.key[a][0]), v1 = key2f(g_qs.key[a][1]);
                    q[a][0] = v0 + f01 * (v1 - v0);
                    v0 = key2f(g_qs.key[a][2]); v1 = key2f(g_qs.key[a][3]);
                    q[a][1] = v0 + f99 * (v1 - v0);
                }
                const float sigma_ratio = (float)(1.0 / 2.355);
                float swf = exp2f(floorf(log2f(1073741824.0f / (float)epb)));
                g_p.SW = swf; g_p.SWinv = 1.0 / (double)swf;
                for (int term = 0; term < 2; term++) {
                    TermP& tp = g_p.tp[term];
                    int pa2 = term, ta2 = 1 - term;
                    float flo = q[ta2][0], fhi = q[ta2][1];
                    tp.flo = flo; tp.fhi = fhi;
                    tp.mlo = q[pa2][0]; tp.mhi = q[pa2][1];
                    float fb = (fhi - flo) / (float)NB;
                    float lo = flo + 0.5f * fb, hi = fhi - 0.5f * fb;
                    float step = (hi - lo) / (float)(NB - 1);
                    float sd = 0.f, prev = lo;
                    for (int i = 1; i < NB; i++) { float v = lo + step * (float)i; sd += v - prev; prev = v; }
                    float fs = (sd / (float)(NB - 1)) * sigma_ratio;
                    float preterm = 1.0f / (2.0f * fs * fs);
                    tp.t0 = lo; tp.is = 1.0f / step;
                    double c = (double)preterm * (double)step * (double)step;
                    double a = 1.0; tp.ac[0] = 1.0f;
                    for (int k = 1; k <= 8; k++) { a *= (-c) / (double)k; tp.ac[k] = (float)a; }
                    double X = 4.0 * c * c;
                    double tm = 1.0; tp.cc[0] = 1.0f;
                    for (int m = 1; m <= 6; m++) { tm *= X / ((double)(2 * m - 1) * (double)(2 * m)); tp.cc[m] = (float)tm; }
                    double st = 2.0 * c; tp.sc[0] = (float)st;
                    for (int m = 1; m <= 6; m++) { st *= X / ((double)(2 * m) * (double)(2 * m + 1)); tp.sc[m] = (float)st; }
                    tp.Qc = (float)exp(-c); tp.Q4c = (float)exp(-4.0 * c);
                    float xm = fmaxf(fabsf(tp.mlo), fabsf(tp.mhi));
                    if (xm < 1e-20f) xm = 1e-20f;
                    float sxs = exp2f(floorf(log2f(1073741824.0f / ((float)epb * xm))));
                    tp.SX = sxs; tp.SXinv = 1.0 / (double)sxs;
                    double nx = (double)N * (double)xm;
                    tp.SSX = exp2(floor(log2(2.3e18 / nx)));
                    tp.SSXinv = 1.0 / tp.SSX;
                    double nxx = nx * (double)xm;
                    tp.SSXX = exp2(floor(log2(2.3e18 / nxx)));
                    tp.SSXXinv = 1.0 / tp.SSXX;
                }
            }
        }
        gridbar();
    }

    // ================= Parzen phase: two single-term passes =================
    parzen_pass(B4, A4, B, A, 0, N, N4, gid, gsz, priv);   // term0: target=B, pred=A
    parzen_pass(A4, B4, A, B, 1, N, N4, gid, gsz, priv);   // term1: target=A, pred=B
    gridbar();

    // ================= final (block 0) =================
    if (blockIdx.x == 0) {
        unsigned long long* stage = dyn;   // reuse smem: [0..63]=H, [64..127]=L, [128..131]=S
        if (t < 64) { stage[t] = g_accH[t]; stage[64 + t] = g_accL[t]; }
        if (t >= 64 && t < 68) stage[128 + (t - 64)] = g_accS[t - 64];
        __syncthreads();
        if (t == 0) {
            const double eps = 1.1920928955078125e-07;
            double dN = (double)N;
            double swi = g_p.SWinv;
            double eta = 0.0;
            for (int term = 0; term < 2; term++) {
                double sxi = g_p.tp[term].SXinv;
                double sx  = (double)(long long)stage[128 + 2 * term]     * g_p.tp[term].SSXinv;
                double sxx = (double)(long long)stage[128 + 2 * term + 1] * g_p.tp[term].SSXXinv;
                double mean = sx / dN;
                double Ssw = 0.0, num = 0.0;
                for (int j = 0; j < NB; j++) {
                    double sw  = (double)stage[term * NB + j] * swi;
                    double swx = (double)(long long)stage[64 + term * NB + j] * sxi;
                    double m = swx / (sw + eps);
                    double d = m - mean;
                    num += sw * d * d;
                    Ssw += sw;
                }
                double bgv = num / (Ssw + eps);
                double var = (sxx - sx * sx / dN) / (dN - 1.0);
                eta += bgv / (var + eps);
            }
            out[0] = (float)(-0.5 * eta);
        }
    }
}

extern "C" void kernel_launch(void* const* d_in, const int* in_sizes, int n_in,
                              void* d_out, int out_size) {
    const float* A = (const float*)d_in[0];
    const float* B = (const float*)d_in[1];
    int N = in_sizes[0];

    double n1 = (double)N - 1.0;
    double p01 = 0.01 * n1, p99 = 0.99 * n1;
    unsigned k01 = (unsigned)p01, k99 = (unsigned)p99;
    float f01 = (float)(p01 - (double)k01);
    float f99 = (float)(p99 - (double)k99);

    cudaFuncSetAttribute(k_fused, cudaFuncAttributeMaxDynamicSharedMemorySize, SMEM_BYTES);
    int bpsm = 0, sms = 0;
    cudaOccupancyMaxActiveBlocksPerMultiprocessor(&bpsm, k_fused, TPB, SMEM_BYTES);
    cudaDeviceGetAttribute(&sms, cudaDevAttrMultiProcessorCount, 0);
    if (bpsm < 1) bpsm = 1;
    long long grid = (long long)bpsm * (long long)sms;
    if (grid > MAXB) grid = MAXB;

    int n4 = N >> 2;
    long long totalT = grid * TPB;
    int iters = (int)((n4 + totalT - 1) / totalT);
    int epb = iters * 4 + 8;

    k_fused<<<(int)grid, TPB, SMEM_BYTES>>>(A, B, N, k01, k99, f01, f99, epb, (float*)d_out);
}